// round 8
// baseline (speedup 1.0000x reference)
#include <cuda_runtime.h>
#include <cuda_bf16.h>
#include <cuda_fp8.h>
#include <math.h>
#include <stdint.h>

#define NROWS 8192
#define DDIM  512
#define TS    128
#define NBLK  (NROWS / TS)        // 64 col-blocks (128 wide)
#define NRB   (NROWS / 256)       // 32 row-blocks (256 tall)
#define KP    96                  // partial slots: [0,64) rowsum by C, [64,96) colsum by R
#define LDAB  80                  // proj smem row stride (32 bf16 + pad)
#define LDS2  144                 // sim smem row stride (128 fp8 + pad)
#define PROJSTG (4 * 128 * LDAB)  // 40960 per proj stage
#define SIMSTG2 ((256 + 128) * LDS2)   // 55296 per sim stage
#define NSYM2 1056                // tiles (R,C), C >= 2R, R<32
#define ZSTRIDE ((size_t)NROWS * DDIM)
#define FP8SCALE 16.0f

// ---------------- device scratch ----------------
__device__ __nv_bfloat16 g_Zh[2 * NROWS * DDIM];
__device__ __nv_bfloat16 g_Zl[2 * NROWS * DDIM];
__device__ __nv_bfloat16 g_Th[2 * NROWS * DDIM];
__device__ __nv_bfloat16 g_Tl[2 * NROWS * DDIM];
__device__ __nv_bfloat16 g_W1h[DDIM * DDIM];
__device__ __nv_bfloat16 g_W1l[DDIM * DDIM];
__device__ __nv_bfloat16 g_W2h[DDIM * DDIM];
__device__ __nv_bfloat16 g_W2l[DDIM * DDIM];
__device__ float g_H [2 * NROWS * DDIM];
__device__ float g_N1[NROWS * DDIM];
__device__ float g_N2[NROWS * DDIM];
__device__ uint8_t g_F1[NROWS * DDIM];   // fp8 e4m3, scaled by 16
__device__ uint8_t g_F2[NROWS * DDIM];
__device__ float g_p11[NROWS * KP];
__device__ float g_p22[NROWS * KP];
__device__ float g_p12[NROWS * KP];
__device__ float g_d12 [NROWS];
__device__ float g_loss[NROWS];

// ====================== helpers ======================
__device__ __forceinline__ uint32_t smem_u32(const void* p) {
    uint32_t a;
    asm("{ .reg .u64 t; cvta.to.shared.u64 t, %1; cvt.u32.u64 %0, t; }"
        : "=r"(a) : "l"(p));
    return a;
}
__device__ __forceinline__ void ldsm_x4(uint32_t (&r)[4], uint32_t addr) {
    asm volatile("ldmatrix.sync.aligned.m8n8.x4.shared.b16 {%0,%1,%2,%3}, [%4];"
        : "=r"(r[0]), "=r"(r[1]), "=r"(r[2]), "=r"(r[3]) : "r"(addr));
}
__device__ __forceinline__ void mma16816(float (&d)[4], const uint32_t (&a)[4],
                                         uint32_t b0, uint32_t b1) {
    asm volatile("mma.sync.aligned.m16n8k16.row.col.f32.bf16.bf16.f32 "
        "{%0,%1,%2,%3}, {%4,%5,%6,%7}, {%8,%9}, {%0,%1,%2,%3};"
        : "+f"(d[0]), "+f"(d[1]), "+f"(d[2]), "+f"(d[3])
        : "r"(a[0]), "r"(a[1]), "r"(a[2]), "r"(a[3]), "r"(b0), "r"(b1));
}
__device__ __forceinline__ void mma16832_fp8(float (&d)[4], const uint32_t (&a)[4],
                                             uint32_t b0, uint32_t b1) {
    asm volatile("mma.sync.aligned.m16n8k32.row.col.f32.e4m3.e4m3.f32 "
        "{%0,%1,%2,%3}, {%4,%5,%6,%7}, {%8,%9}, {%0,%1,%2,%3};"
        : "+f"(d[0]), "+f"(d[1]), "+f"(d[2]), "+f"(d[3])
        : "r"(a[0]), "r"(a[1]), "r"(a[2]), "r"(a[3]), "r"(b0), "r"(b1));
}
#define CP16(dst, src) \
    asm volatile("cp.async.cg.shared.global [%0], [%1], 16;" :: "r"(dst), "l"(src))
#define CPCOMMIT() asm volatile("cp.async.commit_group;" ::: "memory")
#define CPWAIT(n)  asm volatile("cp.async.wait_group %0;" :: "n"(n) : "memory")

__device__ __forceinline__ float fast_exp2(float x) {
    float y; asm("ex2.approx.f32 %0, %1;" : "=f"(y) : "f"(x)); return y;
}
__device__ __forceinline__ void split2(float x, __nv_bfloat16& h, __nv_bfloat16& l) {
    h = __float2bfloat16(x);
    l = __float2bfloat16(x - __bfloat162float(h));
}

// ================== split kernel: fp32 -> (hi, lo) bf16 ==================
__global__ void __launch_bounds__(256)
split_kernel(const float* __restrict__ X, __nv_bfloat16* __restrict__ Hi,
             __nv_bfloat16* __restrict__ Lo) {
    const int i = (blockIdx.x * 256 + threadIdx.x) * 4;
    float4 v = *(const float4*)(X + i);
    __nv_bfloat16 h0, h1, h2, h3, l0, l1, l2, l3;
    split2(v.x, h0, l0); split2(v.y, h1, l1);
    split2(v.z, h2, l2); split2(v.w, h3, l3);
    __nv_bfloat162 hp0 = {h0, h1}, hp1 = {h2, h3};
    __nv_bfloat162 lp0 = {l0, l1}, lp1 = {l2, l3};
    *(uint2*)(Hi + i) = make_uint2(*(uint32_t*)&hp0, *(uint32_t*)&hp1);
    *(uint2*)(Lo + i) = make_uint2(*(uint32_t*)&lp0, *(uint32_t*)&lp1);
}

// ============ split-bf16 projection GEMM (2-stage cp.async, z-batched) =====
template <bool DO_ELU, bool SPLIT_OUT>
__global__ void __launch_bounds__(256, 2)
proj_mma_kernel(const __nv_bfloat16* __restrict__ Ah, const __nv_bfloat16* __restrict__ Al,
                const __nv_bfloat16* __restrict__ Wh, const __nv_bfloat16* __restrict__ Wl,
                const float* __restrict__ bias,
                float* __restrict__ Hout,
                __nv_bfloat16* __restrict__ Oh, __nv_bfloat16* __restrict__ Ol) {
    extern __shared__ __align__(128) char dynsm[];
    const uint32_t s0 = smem_u32(dynsm);

    const int tid = threadIdx.x, lane = tid & 31, wid = tid >> 5;
    const int warp_m = wid & 3, warp_n = wid >> 2;
    const int cb = blockIdx.x, rb = blockIdx.y;
    const size_t zoff = (size_t)blockIdx.z * ZSTRIDE;

    const char* Agh = (const char*)(Ah + zoff + (size_t)rb * TS * DDIM);
    const char* Agl = (const char*)(Al + zoff + (size_t)rb * TS * DDIM);
    const char* Wgh = (const char*)(Wh + (size_t)cb * TS * DDIM);
    const char* Wgl = (const char*)(Wl + (size_t)cb * TS * DDIM);

    const int r0 = tid >> 2, p0 = tid & 3;
    const uint32_t so0 = (uint32_t)(r0 * LDAB + p0 * 16);
    const uint32_t so1 = so0 + 64 * LDAB;

    const int q = lane >> 3, rr = lane & 7;
    const uint32_t lds_off = (uint32_t)(((q & 1) * 8 + rr) * LDAB + (q >> 1) * 16);
    const uint32_t am_off = (uint32_t)(warp_m * 32) * LDAB + lds_off;
    const uint32_t wn_off = (uint32_t)(warp_n * 64) * LDAB + lds_off;

    float acc[2][8][4] = {};

    auto load_chunk = [&](int kc, int stg) {
        const size_t g0 = (size_t)r0 * (DDIM * 2) + (size_t)kc * 64 + p0 * 16;
        const size_t g1 = g0 + (size_t)64 * (DDIM * 2);
        const uint32_t b = s0 + stg * PROJSTG;
        CP16(b + so0,                  Agh + g0);
        CP16(b + so1,                  Agh + g1);
        CP16(b + 128 * LDAB + so0,     Agl + g0);
        CP16(b + 128 * LDAB + so1,     Agl + g1);
        CP16(b + 2 * 128 * LDAB + so0, Wgh + g0);
        CP16(b + 2 * 128 * LDAB + so1, Wgh + g1);
        CP16(b + 3 * 128 * LDAB + so0, Wgl + g0);
        CP16(b + 3 * 128 * LDAB + so1, Wgl + g1);
        CPCOMMIT();
    };

    load_chunk(0, 0);
    for (int kc = 0; kc < 16; kc++) {
        if (kc + 1 < 16) load_chunk(kc + 1, (kc + 1) & 1);
        if (kc < 15) { CPWAIT(1); } else { CPWAIT(0); }
        __syncthreads();
        const uint32_t b = s0 + (kc & 1) * PROJSTG;
        const uint32_t ah_base = b + am_off;
        const uint32_t al_base = b + 128 * LDAB + am_off;
        const uint32_t bh_base = b + 2 * 128 * LDAB + wn_off;
        const uint32_t bl_base = b + 3 * 128 * LDAB + wn_off;
#pragma unroll
        for (int kk = 0; kk < 2; kk++) {
            uint32_t ah[2][4], al[2][4];
            ldsm_x4(ah[0], ah_base + kk * 32);
            ldsm_x4(ah[1], ah_base + 16 * LDAB + kk * 32);
            ldsm_x4(al[0], al_base + kk * 32);
            ldsm_x4(al[1], al_base + 16 * LDAB + kk * 32);
#pragma unroll
            for (int n2 = 0; n2 < 4; n2++) {
                uint32_t bh[4], bl[4];
                ldsm_x4(bh, bh_base + n2 * 16 * LDAB + kk * 32);
                ldsm_x4(bl, bl_base + n2 * 16 * LDAB + kk * 32);
#pragma unroll
                for (int mt = 0; mt < 2; mt++)
#pragma unroll
                    for (int u = 0; u < 2; u++) {
                        const int nt = n2 * 2 + u;
                        mma16816(acc[mt][nt], ah[mt], bh[u], bh[u + 2]);
                        mma16816(acc[mt][nt], ah[mt], bl[u], bl[u + 2]);
                        mma16816(acc[mt][nt], al[mt], bh[u], bh[u + 2]);
                    }
            }
        }
        __syncthreads();
    }

    // ---- epilogue ----
    const int cbase = cb * TS + warp_n * 64;
    const int rbase = rb * TS + warp_m * 32 + (lane >> 2);
#pragma unroll
    for (int mt = 0; mt < 2; mt++) {
        const int ra = rbase + mt * 16, rbb = ra + 8;
#pragma unroll
        for (int nt = 0; nt < 8; nt++) {
            const int c = cbase + nt * 8 + (lane & 3) * 2;
            const float bv0 = bias[c], bv1 = bias[c + 1];
            float x00 = acc[mt][nt][0] + bv0, x01 = acc[mt][nt][1] + bv1;
            float x10 = acc[mt][nt][2] + bv0, x11 = acc[mt][nt][3] + bv1;
            if (DO_ELU) {
                x00 = (x00 > 0.0f) ? x00 : expm1f(x00);
                x01 = (x01 > 0.0f) ? x01 : expm1f(x01);
                x10 = (x10 > 0.0f) ? x10 : expm1f(x10);
                x11 = (x11 > 0.0f) ? x11 : expm1f(x11);
            }
            if (SPLIT_OUT) {
                __nv_bfloat16 h0, h1, l0, l1;
                split2(x00, h0, l0); split2(x01, h1, l1);
                __nv_bfloat162 hp = {h0, h1}, lp = {l0, l1};
                *(uint32_t*)(Oh + zoff + (size_t)ra * DDIM + c) = *(uint32_t*)&hp;
                *(uint32_t*)(Ol + zoff + (size_t)ra * DDIM + c) = *(uint32_t*)&lp;
                split2(x10, h0, l0); split2(x11, h1, l1);
                __nv_bfloat162 hq = {h0, h1}, lq = {l0, l1};
                *(uint32_t*)(Oh + zoff + (size_t)rbb * DDIM + c) = *(uint32_t*)&hq;
                *(uint32_t*)(Ol + zoff + (size_t)rbb * DDIM + c) = *(uint32_t*)&lq;
            } else {
                *(float2*)(Hout + zoff + (size_t)ra  * DDIM + c) = make_float2(x00, x01);
                *(float2*)(Hout + zoff + (size_t)rbb * DDIM + c) = make_float2(x10, x11);
            }
        }
    }
}

// ====== unified similarity kernel: 256x128 tiles, fp8, 3-stage cp.async ====
// bid < 2*NSYM2 : symmetric tiles (R,C) with C >= 2R on F1 (z=0) / F2 (z=1);
//                 per-element masks handle the diagonal straddle.
// else          : S12 tiles (R 0..31, C 0..63), unmasked.
// Partials: p[row*96 + C] (rowsum) and p[col*96 + 64+R] (colsum) — each valid
// slot written exactly once; rowloss skips invalid slots.
__global__ void __launch_bounds__(256, 1)
sim_all_kernel(const uint8_t* __restrict__ F1, const uint8_t* __restrict__ F2,
               float* __restrict__ p11, float* __restrict__ p22,
               float* __restrict__ p12) {
    extern __shared__ __align__(128) char dynsm[];
    const uint32_t s0 = smem_u32(dynsm);
    const int bid = blockIdx.x;
    const int tid = threadIdx.x, lane = tid & 31, wid = tid >> 5;
    const int warp_m = wid & 3;    // 64-row quadrant
    const int warp_n = wid >> 2;   // 64-col half

    int R, C;
    bool sym;
    const uint8_t *A, *B;
    float* rsp;
    if (bid < 2 * NSYM2) {
        sym = true;
        const int z = (bid >= NSYM2) ? 1 : 0;
        const int idx = bid - z * NSYM2;
        int r = 0;
        while (r < 31 && (r + 1) * (65 - (r + 1)) <= idx) r++;
        R = r;
        C = 2 * r + (idx - r * (65 - r));
        A = z ? F2 : F1;
        B = A;
        rsp = z ? p22 : p11;
    } else {
        sym = false;
        const int idx = bid - 2 * NSYM2;
        R = idx >> 6;
        C = idx & 63;
        A = F1; B = F2;
        rsp = p12;
    }

    const char* Ag = (const char*)(A + (size_t)R * 256 * DDIM);
    const char* Bg = (const char*)(B + (size_t)C * 128 * DDIM);

    const int q = lane >> 3, rr = lane & 7;
    const uint32_t lds_off = (uint32_t)(((q & 1) * 8 + rr) * LDS2 + (q >> 1) * 16);
    const uint32_t am_off = (uint32_t)(warp_m * 64) * LDS2 + lds_off;
    const uint32_t bn_off = 256u * LDS2 + (uint32_t)(warp_n * 64) * LDS2 + lds_off;

    auto load_chunk = [&](int kc, int stg) {
        const uint32_t b = s0 + stg * SIMSTG2;
#pragma unroll
        for (int it = 0; it < 12; it++) {
            const int u = it * 256 + tid;
            if (it < 8) {
                const int row = u >> 3, g = u & 7;
                CP16(b + row * LDS2 + g * 16, Ag + (size_t)row * DDIM + kc * 128 + g * 16);
            } else {
                const int row = (u - 2048) >> 3, g = u & 7;
                CP16(b + 256 * LDS2 + row * LDS2 + g * 16,
                     Bg + (size_t)row * DDIM + kc * 128 + g * 16);
            }
        }
        CPCOMMIT();
    };

    float acc[4][8][4] = {};

    load_chunk(0, 0);
    load_chunk(1, 1);
    int cur = 0;
    for (int c = 0; c < 4; c++) {
        if (c < 3) { CPWAIT(1); } else { CPWAIT(0); }
        __syncthreads();
        if (c + 2 < 4) load_chunk(c + 2, (c + 2) % 3);
        const uint32_t b = s0 + cur * SIMSTG2;
        const uint32_t a_base = b + am_off;
        const uint32_t b_base = b + bn_off;
#pragma unroll
        for (int kk = 0; kk < 4; kk++) {
            uint32_t af[4][4], bf[4][4];
#pragma unroll
            for (int mt = 0; mt < 4; mt++)
                ldsm_x4(af[mt], a_base + mt * 16 * LDS2 + kk * 32);
#pragma unroll
            for (int n2 = 0; n2 < 4; n2++)
                ldsm_x4(bf[n2], b_base + n2 * 16 * LDS2 + kk * 32);
#pragma unroll
            for (int mt = 0; mt < 4; mt++)
#pragma unroll
                for (int n2 = 0; n2 < 4; n2++)
#pragma unroll
                    for (int u = 0; u < 2; u++)
                        mma16832_fp8(acc[mt][n2 * 2 + u], af[mt], bf[n2][u], bf[n2][u + 2]);
        }
        cur = (cur + 1 == 3) ? 0 : cur + 1;
    }
    __syncthreads();   // smem reusable for reductions

    // ---- epilogue: exp + masked row/col accumulation ----
    float* rs_sm = (float*)dynsm;            // [256][2]
    float* cs_sm = (float*)(dynsm + 2048);   // [4][128]
    const float CE = 2.8853900817779268f / (FP8SCALE * FP8SCALE);
    const int i0 = R * 256 + warp_m * 64 + (lane >> 2);
    const int j0 = C * 128 + warp_n * 64 + (lane & 3) * 2;

    float rs_acc[4][2] = {};
    float cs2[8][2] = {};
#pragma unroll
    for (int mt = 0; mt < 4; mt++)
#pragma unroll
        for (int nt = 0; nt < 8; nt++)
#pragma unroll
            for (int e = 0; e < 4; e++) {
                float ev = fast_exp2(acc[mt][nt][e] * CE);
                const int i = i0 + mt * 16 + (e >> 1) * 8;
                const int j = j0 + nt * 8 + (e & 1);
                const bool up = !sym || (j >= i);
                const bool st = !sym || (j > i);
                rs_acc[mt][e >> 1] += up ? ev : 0.0f;
                cs2[nt][e & 1]     += st ? ev : 0.0f;
            }

#pragma unroll
    for (int mt = 0; mt < 4; mt++)
#pragma unroll
        for (int half = 0; half < 2; half++) {
            float v = rs_acc[mt][half];
            v += __shfl_xor_sync(0xffffffffu, v, 1);
            v += __shfl_xor_sync(0xffffffffu, v, 2);
            if ((lane & 3) == 0) {
                const int rl = warp_m * 64 + mt * 16 + half * 8 + (lane >> 2);
                rs_sm[rl * 2 + warp_n] = v;
            }
        }
#pragma unroll
    for (int nt = 0; nt < 8; nt++)
#pragma unroll
        for (int e = 0; e < 2; e++) {
            float v = cs2[nt][e];
            v += __shfl_xor_sync(0xffffffffu, v, 4);
            v += __shfl_xor_sync(0xffffffffu, v, 8);
            v += __shfl_xor_sync(0xffffffffu, v, 16);
            if (lane < 4) {
                const int cl = warp_n * 64 + nt * 8 + lane * 2 + e;
                cs_sm[warp_m * 128 + cl] = v;
            }
        }
    __syncthreads();

    {
        const int rg = R * 256 + tid;
        rsp[(size_t)rg * KP + C] = rs_sm[tid * 2] + rs_sm[tid * 2 + 1];
    }
    if (tid < 128) {
        const int cg = C * 128 + tid;
        rsp[(size_t)cg * KP + 64 + R] =
            cs_sm[tid] + cs_sm[128 + tid] + cs_sm[256 + tid] + cs_sm[384 + tid];
    }
}

// ------------- row L2-normalize (z-batched) -> fp32 + scaled fp8 ----------
__global__ void __launch_bounds__(256)
normalize_kernel(const float* __restrict__ H, float* __restrict__ O1,
                 float* __restrict__ O2, uint8_t* __restrict__ F1,
                 uint8_t* __restrict__ F2) {
    const int z = blockIdx.y;
    const int row  = blockIdx.x * 8 + (threadIdx.x >> 5);
    const int lane = threadIdx.x & 31;
    float* O = z ? O2 : O1;
    uint8_t* F = z ? F2 : F1;
    const float4* hp = (const float4*)(H + (size_t)z * ZSTRIDE + (size_t)row * DDIM);
    float4* op = (float4*)(O + (size_t)row * DDIM);
    float4 v[4];
    float ss = 0.0f;
#pragma unroll
    for (int m = 0; m < 4; m++) {
        v[m] = hp[lane + 32 * m];
        ss += v[m].x * v[m].x + v[m].y * v[m].y + v[m].z * v[m].z + v[m].w * v[m].w;
    }
#pragma unroll
    for (int o = 16; o > 0; o >>= 1) ss += __shfl_xor_sync(0xffffffffu, ss, o);
    const float inv = 1.0f / fmaxf(sqrtf(ss), 1e-12f);
#pragma unroll
    for (int m = 0; m < 4; m++) {
        float4 w = v[m];
        w.x *= inv; w.y *= inv; w.z *= inv; w.w *= inv;
        op[lane + 32 * m] = w;
        __nv_fp8x2_storage_t lo = __nv_cvt_float2_to_fp8x2(
            make_float2(w.x * FP8SCALE, w.y * FP8SCALE), __NV_SATFINITE, __NV_E4M3);
        __nv_fp8x2_storage_t hi = __nv_cvt_float2_to_fp8x2(
            make_float2(w.z * FP8SCALE, w.w * FP8SCALE), __NV_SATFINITE, __NV_E4M3);
        uint32_t pk = (uint32_t)lo | ((uint32_t)hi << 16);
        *(uint32_t*)(F + (size_t)row * DDIM + (lane + 32 * m) * 4) = pk;
    }
}

__global__ void __launch_bounds__(256)
d12_kernel(const float* __restrict__ N1, const float* __restrict__ N2,
           float* __restrict__ d12) {
    const int row  = blockIdx.x * 8 + (threadIdx.x >> 5);
    const int lane = threadIdx.x & 31;
    const float4* a = (const float4*)(N1 + (size_t)row * DDIM);
    const float4* b = (const float4*)(N2 + (size_t)row * DDIM);
    float s = 0.0f;
#pragma unroll
    for (int m = 0; m < 4; m++) {
        float4 x = a[lane + 32 * m], y = b[lane + 32 * m];
        s += x.x * y.x + x.y * y.y + x.z * y.z + x.w * y.w;
    }
#pragma unroll
    for (int o = 16; o > 0; o >>= 1) s += __shfl_xor_sync(0xffffffffu, s, o);
    if (lane == 0) d12[row] = s;
}

// per-row loss; validity masks skip never-written partial slots
__global__ void __launch_bounds__(256)
rowloss_kernel(const float* __restrict__ p11, const float* __restrict__ p22,
               const float* __restrict__ p12,
               const float* __restrict__ d12, float* __restrict__ loss) {
    const int row  = blockIdx.x * 8 + (threadIdx.x >> 5);
    const int lane = threadIdx.x & 31;
    const int Rj = row >> 8;          // 256-row block
    float s11 = 0.0f, s22 = 0.0f, s12 = 0.0f, c12 = 0.0f;
#pragma unroll
    for (int it = 0; it < 3; it++) {
        const int m = it * 32 + lane;
        const size_t o = (size_t)row * KP + m;
        bool vsym;
        if (m < 64) vsym = (m >= 2 * Rj);
        else        vsym = ((m - 64) <= Rj);
        if (vsym) { s11 += p11[o]; s22 += p22[o]; }
        if (m < 64) s12 += p12[o];
        else        c12 += p12[o];
    }
#pragma unroll
    for (int o = 16; o > 0; o >>= 1) {
        s11 += __shfl_xor_sync(0xffffffffu, s11, o);
        s22 += __shfl_xor_sync(0xffffffffu, s22, o);
        s12 += __shfl_xor_sync(0xffffffffu, s12, o);
        c12 += __shfl_xor_sync(0xffffffffu, c12, o);
    }
    if (lane == 0) {
        const float E2 = 7.38905609893065f;   // exp(1/tau)
        const float den1 = s11 + s12 - E2;
        const float den2 = s22 + c12 - E2;
        loss[row] = -2.0f * d12[row] + 0.5f * (__logf(den1) + __logf(den2));
    }
}

__global__ void __launch_bounds__(1024)
final_kernel(const float* __restrict__ loss, float* __restrict__ out) {
    __shared__ float sm[1024];
    const int t = threadIdx.x;
    float s = 0.0f;
    for (int i = t; i < NROWS; i += 1024) s += loss[i];
    sm[t] = s;
    __syncthreads();
    for (int o = 512; o > 0; o >>= 1) {
        if (t < o) sm[t] += sm[t + o];
        __syncthreads();
    }
    if (t == 0) out[0] = sm[0] * (1.0f / NROWS);
}

// ---------------- launch ----------------------------------------------------
extern "C" void kernel_launch(void* const* d_in, const int* in_sizes, int n_in,
                              void* d_out, int out_size) {
    const float* pri = (const float*)d_in[0];
    const float* aux = (const float*)d_in[1];
    const float* W1  = (const float*)d_in[2];
    const float* b1  = (const float*)d_in[3];
    const float* W2  = (const float*)d_in[4];
    const float* b2  = (const float*)d_in[5];
    float* out = (float*)d_out;

    __nv_bfloat16 *Zh, *Zl, *Th, *Tl, *W1h, *W1l, *W2h, *W2l;
    uint8_t *F1, *F2;
    float *H, *N1, *N2, *p11, *p22, *p12, *d12, *loss;
    cudaGetSymbolAddress((void**)&Zh,  g_Zh);
    cudaGetSymbolAddress((void**)&Zl,  g_Zl);
    cudaGetSymbolAddress((void**)&Th,  g_Th);
    cudaGetSymbolAddress((void**)&Tl,  g_Tl);
    cudaGetSymbolAddress((void**)&W1h, g_W1h);
    cudaGetSymbolAddress((void**)&W1l, g_W1l);
    cudaGetSymbolAddress((void**)&W2h, g_W2h);
    cudaGetSymbolAddress((void**)&W2l, g_W2l);
    cudaGetSymbolAddress((void**)&H,   g_H);
    cudaGetSymbolAddress((void**)&N1,  g_N1);
    cudaGetSymbolAddress((void**)&N2,  g_N2);
    cudaGetSymbolAddress((void**)&F1,  g_F1);
    cudaGetSymbolAddress((void**)&F2,  g_F2);
    cudaGetSymbolAddress((void**)&p11, g_p11);
    cudaGetSymbolAddress((void**)&p22, g_p22);
    cudaGetSymbolAddress((void**)&p12, g_p12);
    cudaGetSymbolAddress((void**)&d12, g_d12);
    cudaGetSymbolAddress((void**)&loss, g_loss);

    const int simSmem  = 3 * SIMSTG2;   // 165888
    const int projSmem = 2 * PROJSTG;   // 81920
    cudaFuncSetAttribute(proj_mma_kernel<true,  true >,
                         cudaFuncAttributeMaxDynamicSharedMemorySize, projSmem);
    cudaFuncSetAttribute(proj_mma_kernel<false, false>,
                         cudaFuncAttributeMaxDynamicSharedMemorySize, projSmem);
    cudaFuncSetAttribute(sim_all_kernel,
                         cudaFuncAttributeMaxDynamicSharedMemorySize, simSmem);

    const dim3 pg(DDIM / TS, NROWS / TS, 2);   // (4, 64, 2)
    const int simBlocks = 2 * NSYM2 + NRB * NBLK;   // 2112 + 2048 = 4160
    const int nW = DDIM * DDIM / 1024;
    const int nZ = NROWS * DDIM / 1024;

    split_kernel<<<nW, 256>>>(W1, W1h, W1l);
    split_kernel<<<nW, 256>>>(W2, W2h, W2l);
    split_kernel<<<nZ, 256>>>(pri, Zh, Zl);
    split_kernel<<<nZ, 256>>>(aux, Zh + ZSTRIDE, Zl + ZSTRIDE);

    proj_mma_kernel<true,  true ><<<pg, 256, projSmem>>>(Zh, Zl, W1h, W1l, b1,
                                                         nullptr, Th, Tl);
    proj_mma_kernel<false, false><<<pg, 256, projSmem>>>(Th, Tl, W2h, W2l, b2,
                                                         H, nullptr, nullptr);
    normalize_kernel<<<dim3(NROWS / 8, 2), 256>>>(H, N1, N2, F1, F2);

    d12_kernel<<<NROWS / 8, 256>>>(N1, N2, d12);

    sim_all_kernel<<<simBlocks, 256, simSmem>>>(F1, F2, p11, p22, p12);

    rowloss_kernel<<<NROWS / 8, 256>>>(p11, p22, p12, d12, loss);
    final_kernel<<<1, 1024>>>(loss, out);
}

// round 9
// speedup vs baseline: 1.2450x; 1.2450x over previous
#include <cuda_runtime.h>
#include <cuda_bf16.h>
#include <cuda_fp8.h>
#include <math.h>
#include <stdint.h>

#define NROWS 8192
#define DDIM  512
#define TS    128
#define NBLK  (NROWS / TS)        // 64
#define LDAB  80                  // smem row stride (bytes)
#define SIMSTG (2 * 128 * LDAB)   // 20480 per stage (A+B chunk)
#define NSYM  (NBLK * (NBLK + 1) / 2)   // 2080
#define ZSTRIDE ((size_t)NROWS * DDIM)
#define FP8SCALE 16.0f

// ---------------- device scratch ----------------
__device__ __nv_bfloat16 g_Zb[2 * NROWS * DDIM];
__device__ __nv_bfloat16 g_Tb[2 * NROWS * DDIM];
__device__ __nv_bfloat16 g_W1b[DDIM * DDIM];
__device__ __nv_bfloat16 g_W2b[DDIM * DDIM];
__device__ float g_H [2 * NROWS * DDIM];
__device__ uint8_t g_F1[NROWS * DDIM];   // fp8 e4m3, scaled by 16
__device__ uint8_t g_F2[NROWS * DDIM];
__device__ float g_rs11p[NROWS * NBLK];
__device__ float g_rs22p[NROWS * NBLK];
__device__ float g_rs12p[NROWS * NBLK];
__device__ float g_cs12p[NROWS * NBLK];
__device__ float g_d12 [NROWS];
__device__ float g_loss[NROWS];

// ====================== helpers ======================
__device__ __forceinline__ uint32_t smem_u32(const void* p) {
    uint32_t a;
    asm("{ .reg .u64 t; cvta.to.shared.u64 t, %1; cvt.u32.u64 %0, t; }"
        : "=r"(a) : "l"(p));
    return a;
}
__device__ __forceinline__ void ldsm_x4(uint32_t (&r)[4], uint32_t addr) {
    asm volatile("ldmatrix.sync.aligned.m8n8.x4.shared.b16 {%0,%1,%2,%3}, [%4];"
        : "=r"(r[0]), "=r"(r[1]), "=r"(r[2]), "=r"(r[3]) : "r"(addr));
}
__device__ __forceinline__ void mma16816(float (&d)[4], const uint32_t (&a)[4],
                                         uint32_t b0, uint32_t b1) {
    asm volatile("mma.sync.aligned.m16n8k16.row.col.f32.bf16.bf16.f32 "
        "{%0,%1,%2,%3}, {%4,%5,%6,%7}, {%8,%9}, {%0,%1,%2,%3};"
        : "+f"(d[0]), "+f"(d[1]), "+f"(d[2]), "+f"(d[3])
        : "r"(a[0]), "r"(a[1]), "r"(a[2]), "r"(a[3]), "r"(b0), "r"(b1));
}
__device__ __forceinline__ void mma16832_fp8(float (&d)[4], const uint32_t (&a)[4],
                                             uint32_t b0, uint32_t b1) {
    asm volatile("mma.sync.aligned.m16n8k32.row.col.f32.e4m3.e4m3.f32 "
        "{%0,%1,%2,%3}, {%4,%5,%6,%7}, {%8,%9}, {%0,%1,%2,%3};"
        : "+f"(d[0]), "+f"(d[1]), "+f"(d[2]), "+f"(d[3])
        : "r"(a[0]), "r"(a[1]), "r"(a[2]), "r"(a[3]), "r"(b0), "r"(b1));
}
#define CP16(dst, src) \
    asm volatile("cp.async.cg.shared.global [%0], [%1], 16;" :: "r"(dst), "l"(src))
#define CPCOMMIT() asm volatile("cp.async.commit_group;" ::: "memory")
#define CPWAIT(n)  asm volatile("cp.async.wait_group %0;" :: "n"(n) : "memory")

__device__ __forceinline__ float fast_exp2(float x) {
    float y; asm("ex2.approx.f32 %0, %1;" : "=f"(y) : "f"(x)); return y;
}

// ================== convert kernels: fp32 -> bf16 ==================
__global__ void __launch_bounds__(256)
convertW_kernel(const float* __restrict__ X, __nv_bfloat16* __restrict__ O) {
    const int i = (blockIdx.x * 256 + threadIdx.x) * 4;
    float4 v = *(const float4*)(X + i);
    __nv_bfloat162 p0 = __floats2bfloat162_rn(v.x, v.y);
    __nv_bfloat162 p1 = __floats2bfloat162_rn(v.z, v.w);
    *(uint2*)(O + i) = make_uint2(*(uint32_t*)&p0, *(uint32_t*)&p1);
}
__global__ void __launch_bounds__(256)
convertZ_kernel(const float* __restrict__ X1, const float* __restrict__ X2,
                __nv_bfloat16* __restrict__ O) {
    const float* X = blockIdx.y ? X2 : X1;
    const int i = (blockIdx.x * 256 + threadIdx.x) * 4;
    float4 v = *(const float4*)(X + i);
    __nv_bfloat162 p0 = __floats2bfloat162_rn(v.x, v.y);
    __nv_bfloat162 p1 = __floats2bfloat162_rn(v.z, v.w);
    *(uint2*)(O + blockIdx.y * ZSTRIDE + i) = make_uint2(*(uint32_t*)&p0, *(uint32_t*)&p1);
}

// ====== shared bf16 128x128 tile GEMM core (3-stage cp.async, NT) ==========
// acc += A_rows(Ag) · B_rows(Bg)^T over K=512 (16 chunks of 32 bf16)
__device__ __forceinline__ void gemm_tile_bf16(const char* Ag, const char* Bg,
                                               uint32_t s0,
                                               float (&acc)[2][8][4],
                                               int tid, int lane, int warp_m, int warp_n) {
    const int r0 = tid >> 2, p0 = tid & 3;
    const uint32_t so0 = (uint32_t)(r0 * LDAB + p0 * 16);
    const uint32_t so1 = so0 + 64 * LDAB;
    const int q = lane >> 3, rr = lane & 7;
    const uint32_t lds_off = (uint32_t)(((q & 1) * 8 + rr) * LDAB + (q >> 1) * 16);
    const uint32_t am_off = (uint32_t)(warp_m * 32) * LDAB + lds_off;
    const uint32_t bn_off = 128 * LDAB + (uint32_t)(warp_n * 64) * LDAB + lds_off;

    auto load_chunk = [&](int kc, int stg) {
        const size_t g0 = (size_t)r0 * (DDIM * 2) + (size_t)kc * 64 + p0 * 16;
        const size_t g1 = g0 + (size_t)64 * (DDIM * 2);
        const uint32_t b = s0 + stg * SIMSTG;
        CP16(b + so0,              Ag + g0);
        CP16(b + so1,              Ag + g1);
        CP16(b + 128 * LDAB + so0, Bg + g0);
        CP16(b + 128 * LDAB + so1, Bg + g1);
        CPCOMMIT();
    };

    load_chunk(0, 0);
    load_chunk(1, 1);
    int cur = 0;
    for (int kc = 0; kc < 16; kc++) {
        if (kc < 15) { CPWAIT(1); } else { CPWAIT(0); }
        __syncthreads();
        if (kc + 2 < 16) {
            int iss = cur + 2; if (iss >= 3) iss -= 3;
            load_chunk(kc + 2, iss);
        }
        const uint32_t b = s0 + cur * SIMSTG;
        const uint32_t a_base = b + am_off;
        const uint32_t b_base = b + bn_off;
#pragma unroll
        for (int kk = 0; kk < 2; kk++) {
            uint32_t af[2][4];
            ldsm_x4(af[0], a_base + kk * 32);
            ldsm_x4(af[1], a_base + 16 * LDAB + kk * 32);
#pragma unroll
            for (int n2 = 0; n2 < 4; n2++) {
                uint32_t bf[4];
                ldsm_x4(bf, b_base + n2 * 16 * LDAB + kk * 32);
#pragma unroll
                for (int mt = 0; mt < 2; mt++)
#pragma unroll
                    for (int u = 0; u < 2; u++)
                        mma16816(acc[mt][n2 * 2 + u], af[mt], bf[u], bf[u + 2]);
            }
        }
        cur = (cur + 1 == 3) ? 0 : cur + 1;
    }
    __syncthreads();
}

// ============ bf16 projection GEMM (z-batched over embeddings) ==============
// OUT = act(A @ W^T + b).  DO_ELU: write bf16 (layer-1 out); else fp32 H.
template <bool DO_ELU>
__global__ void __launch_bounds__(256, 2)
proj_kernel(const __nv_bfloat16* __restrict__ A, const __nv_bfloat16* __restrict__ W,
            const float* __restrict__ bias,
            float* __restrict__ Hout, __nv_bfloat16* __restrict__ Ob) {
    extern __shared__ __align__(128) char dynsm[];
    const int tid = threadIdx.x, lane = tid & 31, wid = tid >> 5;
    const int warp_m = wid & 3, warp_n = wid >> 2;
    const int cb = blockIdx.x, rb = blockIdx.y;
    const size_t zoff = (size_t)blockIdx.z * ZSTRIDE;

    float acc[2][8][4] = {};
    gemm_tile_bf16((const char*)(A + zoff + (size_t)rb * TS * DDIM),
                   (const char*)(W + (size_t)cb * TS * DDIM),
                   smem_u32(dynsm), acc, tid, lane, warp_m, warp_n);

    const int cbase = cb * TS + warp_n * 64;
    const int rbase = rb * TS + warp_m * 32 + (lane >> 2);
#pragma unroll
    for (int mt = 0; mt < 2; mt++) {
        const int ra = rbase + mt * 16, rbb = ra + 8;
#pragma unroll
        for (int nt = 0; nt < 8; nt++) {
            const int c = cbase + nt * 8 + (lane & 3) * 2;
            const float bv0 = bias[c], bv1 = bias[c + 1];
            float x00 = acc[mt][nt][0] + bv0, x01 = acc[mt][nt][1] + bv1;
            float x10 = acc[mt][nt][2] + bv0, x11 = acc[mt][nt][3] + bv1;
            if (DO_ELU) {
                x00 = (x00 > 0.0f) ? x00 : expm1f(x00);
                x01 = (x01 > 0.0f) ? x01 : expm1f(x01);
                x10 = (x10 > 0.0f) ? x10 : expm1f(x10);
                x11 = (x11 > 0.0f) ? x11 : expm1f(x11);
                __nv_bfloat162 p = __floats2bfloat162_rn(x00, x01);
                __nv_bfloat162 q2 = __floats2bfloat162_rn(x10, x11);
                *(uint32_t*)(Ob + zoff + (size_t)ra  * DDIM + c) = *(uint32_t*)&p;
                *(uint32_t*)(Ob + zoff + (size_t)rbb * DDIM + c) = *(uint32_t*)&q2;
            } else {
                *(float2*)(Hout + zoff + (size_t)ra  * DDIM + c) = make_float2(x00, x01);
                *(float2*)(Hout + zoff + (size_t)rbb * DDIM + c) = make_float2(x10, x11);
            }
        }
    }
}

// ============== similarity tile core (fp8, 3-stage cp.async) ===============
__device__ __forceinline__ void sim_tile_mma_fp8(const char* Ag, const char* Bg,
                                                 uint32_t s0,
                                                 float (&acc)[2][8][4],
                                                 int tid, int lane, int warp_m, int warp_n) {
    const int r0 = tid >> 2, p0 = tid & 3;
    const uint32_t so0 = (uint32_t)(r0 * LDAB + p0 * 16);
    const uint32_t so1 = so0 + 64 * LDAB;
    const int q = lane >> 3, rr = lane & 7;
    const uint32_t lds_off = (uint32_t)(((q & 1) * 8 + rr) * LDAB + (q >> 1) * 16);
    const uint32_t am_off = (uint32_t)(warp_m * 32) * LDAB + lds_off;
    const uint32_t bn_off = 128 * LDAB + (uint32_t)(warp_n * 64) * LDAB + lds_off;

    auto load_chunk = [&](int kc, int stg) {
        const size_t g0 = (size_t)r0 * DDIM + (size_t)kc * 64 + p0 * 16;
        const size_t g1 = g0 + (size_t)64 * DDIM;
        const uint32_t b = s0 + stg * SIMSTG;
        CP16(b + so0,              Ag + g0);
        CP16(b + so1,              Ag + g1);
        CP16(b + 128 * LDAB + so0, Bg + g0);
        CP16(b + 128 * LDAB + so1, Bg + g1);
        CPCOMMIT();
    };

    load_chunk(0, 0);
    load_chunk(1, 1);
    int cur = 0;
    for (int kc = 0; kc < 8; kc++) {
        if (kc < 7) { CPWAIT(1); } else { CPWAIT(0); }
        __syncthreads();
        if (kc + 2 < 8) {
            int iss = cur + 2; if (iss >= 3) iss -= 3;
            load_chunk(kc + 2, iss);
        }
        const uint32_t b = s0 + cur * SIMSTG;
        const uint32_t a_base = b + am_off;
        const uint32_t b_base = b + bn_off;
#pragma unroll
        for (int kk = 0; kk < 2; kk++) {
            uint32_t af[2][4];
            ldsm_x4(af[0], a_base + kk * 32);
            ldsm_x4(af[1], a_base + 16 * LDAB + kk * 32);
#pragma unroll
            for (int n2 = 0; n2 < 4; n2++) {
                uint32_t bf[4];
                ldsm_x4(bf, b_base + n2 * 16 * LDAB + kk * 32);
#pragma unroll
                for (int mt = 0; mt < 2; mt++)
#pragma unroll
                    for (int u = 0; u < 2; u++)
                        mma16832_fp8(acc[mt][n2 * 2 + u], af[mt], bf[u], bf[u + 2]);
            }
        }
        cur = (cur + 1 == 3) ? 0 : cur + 1;
    }
    __syncthreads();
}

// exp + row/col reductions (acc holds dot * 256)
__device__ __forceinline__ void sim_reduce(float (&acc)[2][8][4], char* sm,
                                           int lane, int warp_m, int warp_n,
                                           bool do_col) {
    float* rs_sm = (float*)sm;
    float* cs_sm = (float*)(sm + 1024);
    const float C = 2.8853900817779268f / (FP8SCALE * FP8SCALE);
    float rs_acc[2][2] = {};
    float cs2[8][2];
    if (do_col)
#pragma unroll
        for (int nt = 0; nt < 8; nt++) cs2[nt][0] = cs2[nt][1] = 0.0f;

#pragma unroll
    for (int mt = 0; mt < 2; mt++)
#pragma unroll
        for (int nt = 0; nt < 8; nt++) {
            float e0 = fast_exp2(acc[mt][nt][0] * C);
            float e1 = fast_exp2(acc[mt][nt][1] * C);
            float e2 = fast_exp2(acc[mt][nt][2] * C);
            float e3 = fast_exp2(acc[mt][nt][3] * C);
            rs_acc[mt][0] += e0 + e1;
            rs_acc[mt][1] += e2 + e3;
            if (do_col) { cs2[nt][0] += e0 + e2; cs2[nt][1] += e1 + e3; }
        }

#pragma unroll
    for (int mt = 0; mt < 2; mt++)
#pragma unroll
        for (int half = 0; half < 2; half++) {
            float v = rs_acc[mt][half];
            v += __shfl_xor_sync(0xffffffffu, v, 1);
            v += __shfl_xor_sync(0xffffffffu, v, 2);
            if ((lane & 3) == 0) {
                int row = warp_m * 32 + mt * 16 + half * 8 + (lane >> 2);
                rs_sm[row * 2 + warp_n] = v;
            }
        }
    if (do_col) {
#pragma unroll
        for (int nt = 0; nt < 8; nt++)
#pragma unroll
            for (int e = 0; e < 2; e++) {
                float v = cs2[nt][e];
                v += __shfl_xor_sync(0xffffffffu, v, 4);
                v += __shfl_xor_sync(0xffffffffu, v, 8);
                v += __shfl_xor_sync(0xffffffffu, v, 16);
                if (lane < 4) {
                    int col = warp_n * 64 + nt * 8 + lane * 2 + e;
                    cs_sm[warp_m * 128 + col] = v;
                }
            }
    }
    __syncthreads();
}

// ============ unified similarity kernel: all 8256 tiles in ONE launch =======
__global__ void __launch_bounds__(256, 2)
sim_all_kernel(const uint8_t* __restrict__ F1, const uint8_t* __restrict__ F2,
               float* __restrict__ rs11p, float* __restrict__ rs22p,
               float* __restrict__ rs12p, float* __restrict__ cs12p) {
    extern __shared__ __align__(128) char dynsm[];
    const int bid = blockIdx.x;
    const int tid = threadIdx.x, lane = tid & 31, wid = tid >> 5;
    const int warp_m = wid & 3, warp_n = wid >> 2;

    const uint8_t *A, *B;
    float *rsp, *csp;
    int rb, cb;
    bool diag = false, sym;

    if (bid < 2 * NSYM) {
        sym = true;
        const int z = (bid >= NSYM) ? 1 : 0;
        const int idx = bid - z * NSYM;
        int r = (int)(NBLK + 0.5f - sqrtf((NBLK + 0.5f) * (NBLK + 0.5f) - 2.0f * idx));
        if (r < 0) r = 0;
        if (r > NBLK - 1) r = NBLK - 1;
#define TRI_BASE(x) ((x) * NBLK - ((x) * ((x) - 1)) / 2)
        while (r + 1 <= NBLK - 1 && TRI_BASE(r + 1) <= idx) r++;
        while (r > 0 && TRI_BASE(r) > idx) r--;
        rb = r;
        cb = r + (idx - TRI_BASE(r));
#undef TRI_BASE
        A = z ? F2 : F1;
        B = A;
        rsp = z ? rs22p : rs11p;
        csp = nullptr;
        diag = (rb == cb);
    } else {
        sym = false;
        const int idx = bid - 2 * NSYM;
        rb = idx >> 6;
        cb = idx & (NBLK - 1);
        A = F1; B = F2;
        rsp = rs12p; csp = cs12p;
    }

    float acc[2][8][4] = {};
    sim_tile_mma_fp8((const char*)(A + (size_t)rb * TS * DDIM),
                     (const char*)(B + (size_t)cb * TS * DDIM),
                     smem_u32(dynsm), acc, tid, lane, warp_m, warp_n);
    sim_reduce(acc, dynsm, lane, warp_m, warp_n, !diag);

    float* rs_sm = (float*)dynsm;
    float* cs_sm = (float*)(dynsm + 1024);
    if (tid < TS) {
        rsp[(size_t)(rb * TS + tid) * NBLK + cb] = rs_sm[tid * 2] + rs_sm[tid * 2 + 1];
        if (!diag) {
            const float ctot = cs_sm[tid] + cs_sm[128 + tid] +
                               cs_sm[256 + tid] + cs_sm[384 + tid];
            if (sym) rsp[(size_t)(cb * TS + tid) * NBLK + rb] = ctot;
            else     csp[(size_t)(cb * TS + tid) * NBLK + rb] = ctot;
        }
    }
}

// ------- fused: L2-normalize both embeddings, d12, fp8-quantize -----------
__global__ void __launch_bounds__(256)
normd12_kernel(const float* __restrict__ H, uint8_t* __restrict__ F1,
               uint8_t* __restrict__ F2, float* __restrict__ d12) {
    const int row  = blockIdx.x * 8 + (threadIdx.x >> 5);
    const int lane = threadIdx.x & 31;
    const float4* h1 = (const float4*)(H + (size_t)row * DDIM);
    const float4* h2 = (const float4*)(H + ZSTRIDE + (size_t)row * DDIM);
    float4 v1[4], v2[4];
    float ss1 = 0.0f, ss2 = 0.0f, dd = 0.0f;
#pragma unroll
    for (int m = 0; m < 4; m++) {
        v1[m] = h1[lane + 32 * m];
        v2[m] = h2[lane + 32 * m];
        ss1 += v1[m].x * v1[m].x + v1[m].y * v1[m].y + v1[m].z * v1[m].z + v1[m].w * v1[m].w;
        ss2 += v2[m].x * v2[m].x + v2[m].y * v2[m].y + v2[m].z * v2[m].z + v2[m].w * v2[m].w;
        dd  += v1[m].x * v2[m].x + v1[m].y * v2[m].y + v1[m].z * v2[m].z + v1[m].w * v2[m].w;
    }
#pragma unroll
    for (int o = 16; o > 0; o >>= 1) {
        ss1 += __shfl_xor_sync(0xffffffffu, ss1, o);
        ss2 += __shfl_xor_sync(0xffffffffu, ss2, o);
        dd  += __shfl_xor_sync(0xffffffffu, dd,  o);
    }
    const float inv1 = 1.0f / fmaxf(sqrtf(ss1), 1e-12f);
    const float inv2 = 1.0f / fmaxf(sqrtf(ss2), 1e-12f);
    const float s1 = inv1 * FP8SCALE, s2 = inv2 * FP8SCALE;
#pragma unroll
    for (int m = 0; m < 4; m++) {
        __nv_fp8x2_storage_t lo1 = __nv_cvt_float2_to_fp8x2(
            make_float2(v1[m].x * s1, v1[m].y * s1), __NV_SATFINITE, __NV_E4M3);
        __nv_fp8x2_storage_t hi1 = __nv_cvt_float2_to_fp8x2(
            make_float2(v1[m].z * s1, v1[m].w * s1), __NV_SATFINITE, __NV_E4M3);
        *(uint32_t*)(F1 + (size_t)row * DDIM + (lane + 32 * m) * 4) =
            (uint32_t)lo1 | ((uint32_t)hi1 << 16);
        __nv_fp8x2_storage_t lo2 = __nv_cvt_float2_to_fp8x2(
            make_float2(v2[m].x * s2, v2[m].y * s2), __NV_SATFINITE, __NV_E4M3);
        __nv_fp8x2_storage_t hi2 = __nv_cvt_float2_to_fp8x2(
            make_float2(v2[m].z * s2, v2[m].w * s2), __NV_SATFINITE, __NV_E4M3);
        *(uint32_t*)(F2 + (size_t)row * DDIM + (lane + 32 * m) * 4) =
            (uint32_t)lo2 | ((uint32_t)hi2 << 16);
    }
    if (lane == 0) d12[row] = dd * inv1 * inv2;
}

__global__ void __launch_bounds__(256)
rowloss_kernel(const float* __restrict__ rs11p, const float* __restrict__ rs22p,
               const float* __restrict__ rs12p, const float* __restrict__ cs12p,
               const float* __restrict__ d12, float* __restrict__ loss) {
    const int row  = blockIdx.x * 8 + (threadIdx.x >> 5);
    const int lane = threadIdx.x & 31;
    float s11 = 0.0f, s22 = 0.0f, s12 = 0.0f, c12 = 0.0f;
    for (int m = lane; m < NBLK; m += 32) {
        const size_t o = (size_t)row * NBLK + m;
        s11 += rs11p[o];
        s22 += rs22p[o];
        s12 += rs12p[o];
        c12 += cs12p[o];
    }
#pragma unroll
    for (int o = 16; o > 0; o >>= 1) {
        s11 += __shfl_xor_sync(0xffffffffu, s11, o);
        s22 += __shfl_xor_sync(0xffffffffu, s22, o);
        s12 += __shfl_xor_sync(0xffffffffu, s12, o);
        c12 += __shfl_xor_sync(0xffffffffu, c12, o);
    }
    if (lane == 0) {
        const float E2 = 7.38905609893065f;   // exp(1/tau)
        const float den1 = s11 + s12 - E2;
        const float den2 = s22 + c12 - E2;
        loss[row] = -2.0f * d12[row] + 0.5f * (__logf(den1) + __logf(den2));
    }
}

__global__ void __launch_bounds__(1024)
final_kernel(const float* __restrict__ loss, float* __restrict__ out) {
    __shared__ float sm[1024];
    const int t = threadIdx.x;
    float s = 0.0f;
    for (int i = t; i < NROWS; i += 1024) s += loss[i];
    sm[t] = s;
    __syncthreads();
    for (int o = 512; o > 0; o >>= 1) {
        if (t < o) sm[t] += sm[t + o];
        __syncthreads();
    }
    if (t == 0) out[0] = sm[0] * (1.0f / NROWS);
}

// ---------------- launch ----------------------------------------------------
extern "C" void kernel_launch(void* const* d_in, const int* in_sizes, int n_in,
                              void* d_out, int out_size) {
    const float* pri = (const float*)d_in[0];
    const float* aux = (const float*)d_in[1];
    const float* W1  = (const float*)d_in[2];
    const float* b1  = (const float*)d_in[3];
    const float* W2  = (const float*)d_in[4];
    const float* b2  = (const float*)d_in[5];
    float* out = (float*)d_out;

    __nv_bfloat16 *Zb, *Tb, *W1b, *W2b;
    uint8_t *F1, *F2;
    float *H, *rs11p, *rs22p, *rs12p, *cs12p, *d12, *loss;
    cudaGetSymbolAddress((void**)&Zb,  g_Zb);
    cudaGetSymbolAddress((void**)&Tb,  g_Tb);
    cudaGetSymbolAddress((void**)&W1b, g_W1b);
    cudaGetSymbolAddress((void**)&W2b, g_W2b);
    cudaGetSymbolAddress((void**)&H,   g_H);
    cudaGetSymbolAddress((void**)&F1,  g_F1);
    cudaGetSymbolAddress((void**)&F2,  g_F2);
    cudaGetSymbolAddress((void**)&rs11p, g_rs11p);
    cudaGetSymbolAddress((void**)&rs22p, g_rs22p);
    cudaGetSymbolAddress((void**)&rs12p, g_rs12p);
    cudaGetSymbolAddress((void**)&cs12p, g_cs12p);
    cudaGetSymbolAddress((void**)&d12,  g_d12);
    cudaGetSymbolAddress((void**)&loss, g_loss);

    const int gemmSmem = 3 * SIMSTG;   // 61440
    cudaFuncSetAttribute(proj_kernel<true >,
                         cudaFuncAttributeMaxDynamicSharedMemorySize, gemmSmem);
    cudaFuncSetAttribute(proj_kernel<false>,
                         cudaFuncAttributeMaxDynamicSharedMemorySize, gemmSmem);
    cudaFuncSetAttribute(sim_all_kernel,
                         cudaFuncAttributeMaxDynamicSharedMemorySize, gemmSmem);

    const dim3 pg(DDIM / TS, NROWS / TS, 2);        // (4, 64, 2)
    const int simBlocks = 2 * NSYM + NBLK * NBLK;   // 8256
    const int nW = DDIM * DDIM / 1024;              // 256
    const int nZ = NROWS * DDIM / 1024;             // 4096

    convertW_kernel<<<nW, 256>>>(W1, W1b);
    convertW_kernel<<<nW, 256>>>(W2, W2b);
    convertZ_kernel<<<dim3(nZ, 2), 256>>>(pri, aux, Zb);

    proj_kernel<true ><<<pg, 256, gemmSmem>>>(Zb, W1b, b1, nullptr, Tb);
    proj_kernel<false><<<pg, 256, gemmSmem>>>(Tb, W2b, b2, H, nullptr);

    normd12_kernel<<<NROWS / 8, 256>>>(H, F1, F2, d12);

    sim_all_kernel<<<simBlocks, 256, gemmSmem>>>(F1, F2, rs11p, rs22p, rs12p, cs12p);

    rowloss_kernel<<<NROWS / 8, 256>>>(rs11p, rs22p, rs12p, cs12p, d12, loss);
    final_kernel<<<1, 1024>>>(loss, out);
}